// round 1
// baseline (speedup 1.0000x reference)
#include <cuda_runtime.h>
#include <cuda_bf16.h>
#include <math.h>

// Problem constants
#define BB 64
#define TT 1024
#define QD 1024
#define CD 512
#define SPLITS 8
#define TCHUNK (TT / SPLITS)   // 128

// Output layout (float32): context[B,CD] | a[B,T] | u_new[B] | sq_new[B]
#define CTX_OFF 0
#define A_OFF   (BB * CD)                 // 32768
#define U_OFF   (A_OFF + BB * TT)         // 98304
#define SQ_OFF  (U_OFF + BB)              // 98368

// Deterministic scratch for split-T partial contexts: [B][SPLITS][CD]
__device__ float g_partial[BB * SPLITS * CD];

// ---------------------------------------------------------------------------
// K1: per-batch alpha update + normalization.
// One block per batch, TT threads. a[t] = ((1-u)*alpha[t] + u*alpha[t-1] + 1e-6)^sq
// normalized by the block-wide sum. Written to the 'a' region of d_out.
// ---------------------------------------------------------------------------
__global__ void __launch_bounds__(1024) k_alpha(
    const float* __restrict__ alpha,
    const float* __restrict__ u,
    const float* __restrict__ sq,
    float* __restrict__ out)
{
    const int b = blockIdx.x;
    const int t = threadIdx.x;

    const float ub  = u[b];
    const float sqb = sq[b];

    const float* arow = alpha + (size_t)b * TT;
    const float prev = (t > 0) ? arow[t - 1] : 0.0f;
    const float base = (1.0f - ub) * arow[t] + ub * prev + 1e-6f;
    const float v = powf(base, sqb);

    __shared__ float red[1024];
    red[t] = v;
    __syncthreads();
    #pragma unroll
    for (int s = 512; s > 0; s >>= 1) {
        if (t < s) red[t] += red[t + s];
        __syncthreads();
    }
    const float inv_sum = 1.0f / red[0];
    out[A_OFF + (size_t)b * TT + t] = v * inv_sum;
}

// ---------------------------------------------------------------------------
// K2: split-T partial context. Grid (SPLITS, B), CD threads.
// Block (s, b) handles t in [s*TCHUNK, (s+1)*TCHUNK). Each thread owns one
// context column c; loads are fully coalesced across the block (CD contiguous
// floats per t). 'a' chunk staged through shared memory (one broadcast read
// per iteration).
// ---------------------------------------------------------------------------
__global__ void __launch_bounds__(CD) k_context_partial(
    const float* __restrict__ inputs,
    const float* __restrict__ out /* reads 'a' region */,
    float* __restrict__ partial)
{
    const int s = blockIdx.x;
    const int b = blockIdx.y;
    const int c = threadIdx.x;

    __shared__ float sa[TCHUNK];
    const int t0 = s * TCHUNK;
    if (c < TCHUNK) sa[c] = out[A_OFF + (size_t)b * TT + t0 + c];
    __syncthreads();

    const float* __restrict__ inp = inputs + ((size_t)b * TT + t0) * CD + c;

    float acc0 = 0.0f, acc1 = 0.0f, acc2 = 0.0f, acc3 = 0.0f;
    #pragma unroll 8
    for (int i = 0; i < TCHUNK; i += 4) {
        acc0 = fmaf(sa[i + 0], inp[(size_t)(i + 0) * CD], acc0);
        acc1 = fmaf(sa[i + 1], inp[(size_t)(i + 1) * CD], acc1);
        acc2 = fmaf(sa[i + 2], inp[(size_t)(i + 2) * CD], acc2);
        acc3 = fmaf(sa[i + 3], inp[(size_t)(i + 3) * CD], acc3);
    }
    partial[((size_t)b * SPLITS + s) * CD + c] = (acc0 + acc1) + (acc2 + acc3);
}

// ---------------------------------------------------------------------------
// K3: reduce split partials -> context, then the two 1536-dim heads:
//   ta = [context(512), query(1024)]
//   u_new  = sigmoid(ta . W_u  + b_u)
//   sq_new = sigmoid(ta . W_sq + b_sq) + 1
// One block per batch, CD threads. Thread c owns context[c], query[c],
// query[512+c]; two smem tree reductions.
// ---------------------------------------------------------------------------
__global__ void __launch_bounds__(CD) k_heads(
    const float* __restrict__ partial,
    const float* __restrict__ query,
    const float* __restrict__ W_u,  const float* __restrict__ b_u,
    const float* __restrict__ W_sq, const float* __restrict__ b_sq,
    float* __restrict__ out)
{
    const int b = blockIdx.x;
    const int c = threadIdx.x;

    float ctx = 0.0f;
    #pragma unroll
    for (int s = 0; s < SPLITS; s++)
        ctx += partial[((size_t)b * SPLITS + s) * CD + c];
    out[CTX_OFF + (size_t)b * CD + c] = ctx;

    const float q0 = query[(size_t)b * QD + c];
    const float q1 = query[(size_t)b * QD + 512 + c];

    float pu = ctx * W_u[c]  + q0 * W_u[512 + c]  + q1 * W_u[1024 + c];
    float ps = ctx * W_sq[c] + q0 * W_sq[512 + c] + q1 * W_sq[1024 + c];

    __shared__ float su[CD];
    __shared__ float ss[CD];
    su[c] = pu;
    ss[c] = ps;
    __syncthreads();
    #pragma unroll
    for (int s = 256; s > 0; s >>= 1) {
        if (c < s) { su[c] += su[c + s]; ss[c] += ss[c + s]; }
        __syncthreads();
    }
    if (c == 0) {
        const float zu = su[0] + b_u[0];
        const float zs = ss[0] + b_sq[0];
        out[U_OFF + b]  = 1.0f / (1.0f + expf(-zu));
        out[SQ_OFF + b] = 1.0f / (1.0f + expf(-zs)) + 1.0f;
    }
}

extern "C" void kernel_launch(void* const* d_in, const int* in_sizes, int n_in,
                              void* d_out, int out_size)
{
    const float* query  = (const float*)d_in[0];  // [B,1,QD]
    const float* inputs = (const float*)d_in[1];  // [B,T,CD]
    const float* alpha  = (const float*)d_in[2];  // [B,T]
    const float* u      = (const float*)d_in[3];  // [B,1]
    const float* sq     = (const float*)d_in[4];  // [B,1]
    const float* W_u    = (const float*)d_in[5];  // [QD+CD,1]
    const float* b_u    = (const float*)d_in[6];  // [1]
    const float* W_sq   = (const float*)d_in[7];  // [QD+CD,1]
    const float* b_sq   = (const float*)d_in[8];  // [1]
    float* out = (float*)d_out;

    float* partial;
    cudaGetSymbolAddress((void**)&partial, g_partial);

    k_alpha<<<BB, TT>>>(alpha, u, sq, out);

    dim3 g2(SPLITS, BB);
    k_context_partial<<<g2, CD>>>(inputs, out, partial);

    k_heads<<<BB, CD>>>(partial, query, W_u, b_u, W_sq, b_sq, out);
}

// round 2
// speedup vs baseline: 1.0817x; 1.0817x over previous
#include <cuda_runtime.h>
#include <cuda_bf16.h>
#include <math.h>

// Problem constants
#define BB 64
#define TT 1024
#define QD 1024
#define CD 512
#define SPLITS 16
#define TCHUNK (TT / SPLITS)   // 64

// Output layout (float32): context[B,CD] | a[B,T] | u_new[B] | sq_new[B]
#define CTX_OFF 0
#define A_OFF   (BB * CD)                 // 32768
#define U_OFF   (A_OFF + BB * TT)         // 98304
#define SQ_OFF  (U_OFF + BB)              // 98368

// Deterministic scratch for split-T partial contexts: [B][SPLITS][CD]
__device__ float g_partial[BB * SPLITS * CD];

// ---------------------------------------------------------------------------
// K1: per-batch alpha update + normalization.
// a[t] = ((1-u)*alpha[t] + u*alpha[t-1] + 1e-6)^sq, normalized over T.
// Fast pow via MUFU (__logf/__expf), warp-shuffle reduction.
// ---------------------------------------------------------------------------
__global__ void __launch_bounds__(1024) k_alpha(
    const float* __restrict__ alpha,
    const float* __restrict__ u,
    const float* __restrict__ sq,
    float* __restrict__ out)
{
    const int b = blockIdx.x;
    const int t = threadIdx.x;
    const int lane = t & 31;
    const int wid  = t >> 5;

    const float ub  = u[b];
    const float sqb = sq[b];

    const float* arow = alpha + (size_t)b * TT;
    const float prev = (t > 0) ? arow[t - 1] : 0.0f;
    const float base = fmaf(-ub, arow[t], arow[t]) + fmaf(ub, prev, 1e-6f);
    // base > 0 always (alpha >= 0, u in (0,1)); fast pow:
    const float v = __expf(sqb * __logf(base));

    // warp reduce
    float s = v;
    #pragma unroll
    for (int o = 16; o > 0; o >>= 1) s += __shfl_xor_sync(0xffffffffu, s, o);

    __shared__ float wsum[32];
    __shared__ float inv_sum_sh;
    if (lane == 0) wsum[wid] = s;
    __syncthreads();
    if (wid == 0) {
        float x = wsum[lane];
        #pragma unroll
        for (int o = 16; o > 0; o >>= 1) x += __shfl_xor_sync(0xffffffffu, x, o);
        if (lane == 0) inv_sum_sh = 1.0f / x;
    }
    __syncthreads();

    out[A_OFF + (size_t)b * TT + t] = v * inv_sum_sh;
}

// ---------------------------------------------------------------------------
// K2: split-T partial context. Grid (SPLITS, B), 128 threads.
// Thread c4 owns float4 column group [4*c4, 4*c4+4). 64 t-steps per block,
// LDG.128 fully coalesced (2 KB per row per block), 4 independent float4
// accumulators for MLP.
// ---------------------------------------------------------------------------
__global__ void __launch_bounds__(128) k_context_partial(
    const float* __restrict__ inputs,
    const float* __restrict__ out /* reads 'a' region */,
    float* __restrict__ partial)
{
    const int s = blockIdx.x;
    const int b = blockIdx.y;
    const int c4 = threadIdx.x;     // 0..127 -> float4 group

    __shared__ float sa[TCHUNK];
    const int t0 = s * TCHUNK;
    if (c4 < TCHUNK) sa[c4] = out[A_OFF + (size_t)b * TT + t0 + c4];
    __syncthreads();

    const float4* __restrict__ inp =
        (const float4*)(inputs + ((size_t)b * TT + t0) * CD) + c4;

    float4 a0 = {0,0,0,0}, a1 = {0,0,0,0}, a2 = {0,0,0,0}, a3 = {0,0,0,0};

    #pragma unroll 4
    for (int i = 0; i < TCHUNK; i += 4) {
        const float4 v0 = inp[(size_t)(i + 0) * (CD/4)];
        const float4 v1 = inp[(size_t)(i + 1) * (CD/4)];
        const float4 v2 = inp[(size_t)(i + 2) * (CD/4)];
        const float4 v3 = inp[(size_t)(i + 3) * (CD/4)];
        const float w0 = sa[i + 0], w1 = sa[i + 1], w2 = sa[i + 2], w3 = sa[i + 3];
        a0.x = fmaf(w0, v0.x, a0.x); a0.y = fmaf(w0, v0.y, a0.y);
        a0.z = fmaf(w0, v0.z, a0.z); a0.w = fmaf(w0, v0.w, a0.w);
        a1.x = fmaf(w1, v1.x, a1.x); a1.y = fmaf(w1, v1.y, a1.y);
        a1.z = fmaf(w1, v1.z, a1.z); a1.w = fmaf(w1, v1.w, a1.w);
        a2.x = fmaf(w2, v2.x, a2.x); a2.y = fmaf(w2, v2.y, a2.y);
        a2.z = fmaf(w2, v2.z, a2.z); a2.w = fmaf(w2, v2.w, a2.w);
        a3.x = fmaf(w3, v3.x, a3.x); a3.y = fmaf(w3, v3.y, a3.y);
        a3.z = fmaf(w3, v3.z, a3.z); a3.w = fmaf(w3, v3.w, a3.w);
    }

    float4 r;
    r.x = (a0.x + a1.x) + (a2.x + a3.x);
    r.y = (a0.y + a1.y) + (a2.y + a3.y);
    r.z = (a0.z + a1.z) + (a2.z + a3.z);
    r.w = (a0.w + a1.w) + (a2.w + a3.w);

    float4* __restrict__ pout =
        (float4*)(partial + ((size_t)b * SPLITS + s) * CD) + c4;
    *pout = r;
}

// ---------------------------------------------------------------------------
// K3: reduce split partials -> context, then the two 1536-dim heads.
// One block per batch, CD threads.
// ---------------------------------------------------------------------------
__global__ void __launch_bounds__(CD) k_heads(
    const float* __restrict__ partial,
    const float* __restrict__ query,
    const float* __restrict__ W_u,  const float* __restrict__ b_u,
    const float* __restrict__ W_sq, const float* __restrict__ b_sq,
    float* __restrict__ out)
{
    const int b = blockIdx.x;
    const int c = threadIdx.x;

    float ctx = 0.0f;
    #pragma unroll
    for (int s = 0; s < SPLITS; s++)
        ctx += partial[((size_t)b * SPLITS + s) * CD + c];
    out[CTX_OFF + (size_t)b * CD + c] = ctx;

    const float q0 = query[(size_t)b * QD + c];
    const float q1 = query[(size_t)b * QD + 512 + c];

    float pu = ctx * W_u[c]  + q0 * W_u[512 + c]  + q1 * W_u[1024 + c];
    float ps = ctx * W_sq[c] + q0 * W_sq[512 + c] + q1 * W_sq[1024 + c];

    __shared__ float su[CD];
    __shared__ float ss[CD];
    su[c] = pu;
    ss[c] = ps;
    __syncthreads();
    #pragma unroll
    for (int s = 256; s > 0; s >>= 1) {
        if (c < s) { su[c] += su[c + s]; ss[c] += ss[c + s]; }
        __syncthreads();
    }
    if (c == 0) {
        const float zu = su[0] + b_u[0];
        const float zs = ss[0] + b_sq[0];
        out[U_OFF + b]  = 1.0f / (1.0f + expf(-zu));
        out[SQ_OFF + b] = 1.0f / (1.0f + expf(-zs)) + 1.0f;
    }
}

extern "C" void kernel_launch(void* const* d_in, const int* in_sizes, int n_in,
                              void* d_out, int out_size)
{
    const float* query  = (const float*)d_in[0];  // [B,1,QD]
    const float* inputs = (const float*)d_in[1];  // [B,T,CD]
    const float* alpha  = (const float*)d_in[2];  // [B,T]
    const float* u      = (const float*)d_in[3];  // [B,1]
    const float* sq     = (const float*)d_in[4];  // [B,1]
    const float* W_u    = (const float*)d_in[5];  // [QD+CD,1]
    const float* b_u    = (const float*)d_in[6];  // [1]
    const float* W_sq   = (const float*)d_in[7];  // [QD+CD,1]
    const float* b_sq   = (const float*)d_in[8];  // [1]
    float* out = (float*)d_out;

    float* partial;
    cudaGetSymbolAddress((void**)&partial, g_partial);

    k_alpha<<<BB, TT>>>(alpha, u, sq, out);

    dim3 g2(SPLITS, BB);
    k_context_partial<<<g2, 128>>>(inputs, out, partial);

    k_heads<<<BB, CD>>>(partial, query, W_u, b_u, W_sq, b_sq, out);
}

// round 3
// speedup vs baseline: 1.1944x; 1.1042x over previous
#include <cuda_runtime.h>
#include <cuda_bf16.h>
#include <math.h>

// Problem constants
#define BB 64
#define TT 1024
#define QD 1024
#define CD 512
#define SPLITS 16
#define TCHUNK (TT / SPLITS)   // 64

// Output layout (float32): context[B,CD] | a[B,T] | u_new[B] | sq_new[B]
#define CTX_OFF 0
#define A_OFF   (BB * CD)                 // 32768
#define U_OFF   (A_OFF + BB * TT)         // 98304
#define SQ_OFF  (U_OFF + BB)              // 98368

// Scratch: partial (unnormalized) contexts and partial v-sums
__device__ float g_partial[BB * SPLITS * CD];
__device__ float g_vsum[BB * SPLITS];

// ---------------------------------------------------------------------------
// K2: fused alpha + split-T partial context. Grid (SPLITS, B), 128 threads.
// Threads 0..63 compute v[t] = ((1-u)*alpha[t] + u*alpha[t-1] + 1e-6)^sq for
// this block's 64 t-values (UNNORMALIZED), stash in smem + write to the 'a'
// region of out, and record the partial sum. All 128 threads then do the
// float4 matvec against inputs (read-once -> __ldcs streaming loads).
// Normalization is deferred to K3 (it commutes with the weighted sum).
// ---------------------------------------------------------------------------
__global__ void __launch_bounds__(128) k_context_partial(
    const float* __restrict__ inputs,
    const float* __restrict__ alpha,
    const float* __restrict__ u,
    const float* __restrict__ sq,
    float* __restrict__ out,
    float* __restrict__ partial,
    float* __restrict__ vsum)
{
    const int s = blockIdx.x;
    const int b = blockIdx.y;
    const int tid = threadIdx.x;
    const int t0 = s * TCHUNK;

    __shared__ float sa[TCHUNK];

    if (tid < TCHUNK) {
        const int t = t0 + tid;
        const float ub  = u[b];
        const float sqb = sq[b];
        const float* arow = alpha + (size_t)b * TT;
        const float cur  = arow[t];
        const float prev = (t > 0) ? arow[t - 1] : 0.0f;
        const float base = fmaf(-ub, cur, cur) + fmaf(ub, prev, 1e-6f);
        const float v = __expf(sqb * __logf(base));   // base > 0 always
        sa[tid] = v;
        out[A_OFF + (size_t)b * TT + t] = v;          // unnormalized; K3 rescales

        // partial sum of v over this chunk (2 warps hold tid 0..63)
        float ss = v;
        #pragma unroll
        for (int o = 16; o > 0; o >>= 1) ss += __shfl_xor_sync(0xffffffffu, ss, o);
        if ((tid & 31) == 0) {
            // two warps -> combine via smem-free trick: warp0 lane0 and warp1 lane0
            // write both halves; K3 sums SPLITS entries anyway, so store per-warp
            // halves into the two halves of one slot? Simpler: atomic-free split:
            vsum[((size_t)b * SPLITS + s) * 2 >= 0 ? ((size_t)b * SPLITS + s) : 0] = 0.0f; // placeholder overwritten below
        }
        __syncwarp();
    }
    __syncthreads();

    // deterministic combine of the two warp sums via smem
    __shared__ float wsum2[2];
    if (tid < TCHUNK && (tid & 31) == 0) {
        float ss = sa[tid & ~31];
        // recompute warp sum cheaply from smem to avoid cross-warp shuffle state
        float acc = 0.0f;
        #pragma unroll
        for (int i = 0; i < 32; i++) acc += sa[(tid & ~31) + i];
        wsum2[tid >> 5] = acc;
        (void)ss;
    }
    __syncthreads();
    if (tid == 0) vsum[(size_t)b * SPLITS + s] = wsum2[0] + wsum2[1];

    const float4* __restrict__ inp =
        (const float4*)(inputs + ((size_t)b * TT + t0) * CD) + tid;

    float4 a0 = {0,0,0,0}, a1 = {0,0,0,0}, a2 = {0,0,0,0}, a3 = {0,0,0,0};

    #pragma unroll 4
    for (int i = 0; i < TCHUNK; i += 4) {
        const float4 v0 = __ldcs(&inp[(size_t)(i + 0) * (CD/4)]);
        const float4 v1 = __ldcs(&inp[(size_t)(i + 1) * (CD/4)]);
        const float4 v2 = __ldcs(&inp[(size_t)(i + 2) * (CD/4)]);
        const float4 v3 = __ldcs(&inp[(size_t)(i + 3) * (CD/4)]);
        const float w0 = sa[i + 0], w1 = sa[i + 1], w2 = sa[i + 2], w3 = sa[i + 3];
        a0.x = fmaf(w0, v0.x, a0.x); a0.y = fmaf(w0, v0.y, a0.y);
        a0.z = fmaf(w0, v0.z, a0.z); a0.w = fmaf(w0, v0.w, a0.w);
        a1.x = fmaf(w1, v1.x, a1.x); a1.y = fmaf(w1, v1.y, a1.y);
        a1.z = fmaf(w1, v1.z, a1.z); a1.w = fmaf(w1, v1.w, a1.w);
        a2.x = fmaf(w2, v2.x, a2.x); a2.y = fmaf(w2, v2.y, a2.y);
        a2.z = fmaf(w2, v2.z, a2.z); a2.w = fmaf(w2, v2.w, a2.w);
        a3.x = fmaf(w3, v3.x, a3.x); a3.y = fmaf(w3, v3.y, a3.y);
        a3.z = fmaf(w3, v3.z, a3.z); a3.w = fmaf(w3, v3.w, a3.w);
    }

    float4 r;
    r.x = (a0.x + a1.x) + (a2.x + a3.x);
    r.y = (a0.y + a1.y) + (a2.y + a3.y);
    r.z = (a0.z + a1.z) + (a2.z + a3.z);
    r.w = (a0.w + a1.w) + (a2.w + a3.w);

    float4* __restrict__ pout =
        (float4*)(partial + ((size_t)b * SPLITS + s) * CD) + tid;
    *pout = r;
}

// ---------------------------------------------------------------------------
// K3: reduce partials + v-sums -> normalized context; rescale 'a' region;
// sigmoid heads. One block per batch, CD threads.
// ---------------------------------------------------------------------------
__global__ void __launch_bounds__(CD) k_heads(
    const float* __restrict__ partial,
    const float* __restrict__ vsum,
    const float* __restrict__ query,
    const float* __restrict__ W_u,  const float* __restrict__ b_u,
    const float* __restrict__ W_sq, const float* __restrict__ b_sq,
    float* __restrict__ out)
{
    const int b = blockIdx.x;
    const int c = threadIdx.x;

    // total v-sum for this batch (every thread computes it; 16 L2-hit loads)
    float S = 0.0f;
    #pragma unroll
    for (int s = 0; s < SPLITS; s++) S += vsum[(size_t)b * SPLITS + s];
    const float inv = 1.0f / S;

    float ctx = 0.0f;
    #pragma unroll
    for (int s = 0; s < SPLITS; s++)
        ctx += partial[((size_t)b * SPLITS + s) * CD + c];
    ctx *= inv;
    out[CTX_OFF + (size_t)b * CD + c] = ctx;

    // rescale the 'a' region in place (TT elements, CD threads -> 2 iters)
    #pragma unroll
    for (int t = c; t < TT; t += CD)
        out[A_OFF + (size_t)b * TT + t] *= inv;

    const float q0 = query[(size_t)b * QD + c];
    const float q1 = query[(size_t)b * QD + 512 + c];

    float pu = ctx * W_u[c]  + q0 * W_u[512 + c]  + q1 * W_u[1024 + c];
    float ps = ctx * W_sq[c] + q0 * W_sq[512 + c] + q1 * W_sq[1024 + c];

    __shared__ float su[CD];
    __shared__ float ss[CD];
    su[c] = pu;
    ss[c] = ps;
    __syncthreads();
    #pragma unroll
    for (int s = 256; s > 0; s >>= 1) {
        if (c < s) { su[c] += su[c + s]; ss[c] += ss[c + s]; }
        __syncthreads();
    }
    if (c == 0) {
        const float zu = su[0] + b_u[0];
        const float zs = ss[0] + b_sq[0];
        out[U_OFF + b]  = 1.0f / (1.0f + expf(-zu));
        out[SQ_OFF + b] = 1.0f / (1.0f + expf(-zs)) + 1.0f;
    }
}

extern "C" void kernel_launch(void* const* d_in, const int* in_sizes, int n_in,
                              void* d_out, int out_size)
{
    const float* query  = (const float*)d_in[0];  // [B,1,QD]
    const float* inputs = (const float*)d_in[1];  // [B,T,CD]
    const float* alpha  = (const float*)d_in[2];  // [B,T]
    const float* u      = (const float*)d_in[3];  // [B,1]
    const float* sq     = (const float*)d_in[4];  // [B,1]
    const float* W_u    = (const float*)d_in[5];  // [QD+CD,1]
    const float* b_u    = (const float*)d_in[6];  // [1]
    const float* W_sq   = (const float*)d_in[7];  // [QD+CD,1]
    const float* b_sq   = (const float*)d_in[8];  // [1]
    float* out = (float*)d_out;

    float* partial;
    float* vsum;
    cudaGetSymbolAddress((void**)&partial, g_partial);
    cudaGetSymbolAddress((void**)&vsum, g_vsum);

    dim3 g2(SPLITS, BB);
    k_context_partial<<<g2, 128>>>(inputs, alpha, u, sq, out, partial, vsum);

    k_heads<<<BB, CD>>>(partial, vsum, query, W_u, b_u, W_sq, b_sq, out);
}